// round 13
// baseline (speedup 1.0000x reference)
#include <cuda_runtime.h>
#include <cuda_fp16.h>
#include <cstdint>
#include <cstddef>

// ---------------- problem constants ----------------
#define BT_N   4096      // B*T
#define F_DIM  256
#define GV     16384     // G*V
#define V_DIM  8192
#define DG     8
#define KK     768       // 3 * F_DIM  (fp16-split GEMM packed along K)

// ---------------- scratch (device globals; no runtime allocation) ----------------
__device__ __half g_E[(size_t)BT_N * GV];               // 134 MB: exp(h) fp16 for marginal
__device__ float  g_part[(size_t)BT_N * 128 * 16];      // 33.5 MB per-(row,tile) partials
__device__ __half g_Asplit[(size_t)BT_N * KK];          // [xh | xh | xl]
__device__ __half g_Bsplit[(size_t)GV   * KK];          // [Wh | Wl | Wh]
__device__ float  g_R[BT_N * 2];                        // mask*inv_msum/Z per (bt,g)
__device__ float  g_marg[GV];                           // marginal accumulator
__device__ float  g_inv_msum;

// ---------------- FFMA log (final kernel) + exp ----------------
__device__ __forceinline__ float my_logf(float a) {
    float m, r, s, t, i, f;
    int e;
    e = (__float_as_int(a) - 0x3f2aaaab) & 0xff800000;
    m = __int_as_float(__float_as_int(a) - e);
    i = (float)e * 1.19209290e-7f;
    f = m - 1.0f;
    s = f * f;
    r = -0.130310059f;
    t =  0.140869141f;
    r = fmaf(r, s, -0.121483512f);
    t = fmaf(t, s,  0.139814854f);
    r = fmaf(r, s, -0.166846126f);
    t = fmaf(t, s,  0.200120345f);
    r = fmaf(r, s, -0.249996200f);
    r = fmaf(t, f, r);
    r = fmaf(r, f,  0.333331972f);
    r = fmaf(r, f, -0.500000000f);
    r = fmaf(r, s, f);
    r = fmaf(i, 0.693147182f, r);
    return r;
}

__device__ __forceinline__ float my_expf(float a) {
    float f, r, j;
    int i;
    j = fmaf(1.442695041f, a, 12582912.f) - 12582912.f;
    f = fmaf(j, -6.93145752e-1f, a);
    f = fmaf(j, -1.42860677e-6f, f);
    i = (int)j;
    r = 1.37805939e-3f;
    r = fmaf(r, f, 8.37312452e-3f);
    r = fmaf(r, f, 4.16695364e-2f);
    r = fmaf(r, f, 1.66664720e-1f);
    r = fmaf(r, f, 4.99999851e-1f);
    r = fmaf(r, f, 1.00000000e+0f);
    r = fmaf(r, f, 1.00000000e+0f);
    r = __int_as_float(__float_as_int(r) + (i << 23));
    return r;
}

// inner = -log(u); hybrid: MUFU for u<0.875, exact-f log1p Taylor for u>=0.875.
__device__ __forceinline__ float neg_log_u(float uu) {
    uu = fmaxf(uu, 1.17549435e-38f);
    float inner_m = -__logf(uu);
    float f = uu - 1.0f;                       // exact for uu >= 0.5 (Sterbenz)
    float q = fmaf(f, -0.125f, 0.14285714f);   // log1p Taylor deg 7
    q = fmaf(q, f, -0.16666667f);
    q = fmaf(q, f,  0.20f);
    q = fmaf(q, f, -0.25f);
    q = fmaf(q, f,  0.33333333f);
    q = fmaf(q, f, -0.5f);
    q = fmaf(q, f,  1.0f);
    float inner_p = -(f * q);
    return (uu >= 0.875f) ? inner_p : inner_m;
}

__device__ __forceinline__ float to_tf32(float x) {
    uint32_t v;
    asm("cvt.rna.tf32.f32 %0, %1;" : "=r"(v) : "f"(x));
    return __uint_as_float(v);
}

// ---------------- prep kernels ----------------
__global__ void prep_split(const float* __restrict__ W, const float* __restrict__ X) {
    int idx = blockIdx.x * blockDim.x + threadIdx.x;
    if (idx < GV * F_DIM) {
        int n = idx >> 8, k = idx & 255;
        float w = W[idx];
        __half hi = __float2half_rn(w);
        __half lo = __float2half_rn(w - __half2float(hi));
        size_t base = (size_t)n * KK;
        g_Bsplit[base + k]        = hi;
        g_Bsplit[base + 256 + k]  = lo;
        g_Bsplit[base + 512 + k]  = hi;
    } else if (idx < GV * F_DIM + BT_N * F_DIM) {
        int j = idx - GV * F_DIM;
        int n = j >> 8, k = j & 255;
        float x = X[j];
        __half hi = __float2half_rn(x);
        __half lo = __float2half_rn(x - __half2float(hi));
        size_t base = (size_t)n * KK;
        g_Asplit[base + k]        = hi;
        g_Asplit[base + 256 + k]  = hi;
        g_Asplit[base + 512 + k]  = lo;
    }
}

__global__ void prep_misc(const int* __restrict__ mask) {
    int t = threadIdx.x;
    for (int i = t; i < GV; i += 256) g_marg[i] = 0.f;
    int s = 0;
    for (int i = t; i < BT_N; i += 256) s += mask[i];
    __shared__ int sm[256];
    sm[t] = s; __syncthreads();
    for (int o = 128; o; o >>= 1) { if (t < o) sm[t] += sm[t + o]; __syncthreads(); }
    if (t == 0) g_inv_msum = 1.0f / (float)sm[0];
}

// ---------------- fused GEMM + epilogue ----------------
// Block tile 128x128, 4 warps, warp tile 64x64, BK=64, 3 stages, 2 CTAs/SM.
// Epilogue v6: U prefetched into freed stages; ey tf32-rounded fp32 written
// in place; cv by m16n8k8 tf32 mma (fp32 operands, no transpose of emb).
#define BM 128
#define BN 128
#define BK 64
#define STAGES 3
#define A_BYTES  (BM * BK * 2)          // 16384
#define STG_BYTES (2 * A_BYTES)         // 32768
#define CVS_OFF  (2 * STG_BYTES)        // cv scratch in dead stage2 (4KB)
#define RED_OFF  (2 * STG_BYTES + 4096) // reductions (4KB)
#define EMBF_OFF (3 * STG_BYTES)        // emb fp32 tile 128x8 = 4KB
#define GEMM_SMEM (EMBF_OFF + 4096)     // 102400

// swizzled byte offset of float2 (row r, col-pair c2) within the 64KB U/ey region
#define USWZ(r, c2) ((r) * 512 + ((((c2) >> 1) ^ ((r) & 7)) << 4) + (((c2) & 1) << 3))

__global__ void __launch_bounds__(128, 2) gemm_kernel(
    const float* __restrict__ bias, const float* __restrict__ U,
    const float* __restrict__ emb)
{
    extern __shared__ __align__(128) char smem[];
    int tid  = threadIdx.x;
    int lane = tid & 31, warp = tid >> 5;
    int wm = warp >> 1, wn = warp & 1;        // 2 x 2 warp grid, warp tile 64x64
    int bm = blockIdx.y, bn = blockIdx.x;
    const __half* gA = g_Asplit + (size_t)bm * BM * KK;
    const __half* gB = g_Bsplit + (size_t)bn * BN * KK;

    const int g  = bn >> 6;
    const int v0 = (bn & 63) * 128;

    auto load_stage = [&](int s, int kt) {
        int k0 = kt * BK;
        char* sa = smem + s * STG_BYTES;
        char* sb = sa + A_BYTES;
        #pragma unroll
        for (int i = 0; i < 8; i++) {
            int idx = tid + 128 * i;       // 0..1023
            int row = idx >> 3, c16 = idx & 7;
            int pc  = c16 ^ (row & 7);
            uint32_t da = (uint32_t)__cvta_generic_to_shared(sa + row * 128 + pc * 16);
            asm volatile("cp.async.cg.shared.global [%0], [%1], 16;\n"
                :: "r"(da), "l"(gA + (size_t)row * KK + k0 + c16 * 8));
            uint32_t db = (uint32_t)__cvta_generic_to_shared(sb + row * 128 + pc * 16);
            asm volatile("cp.async.cg.shared.global [%0], [%1], 16;\n"
                :: "r"(db), "l"(gB + (size_t)row * KK + k0 + c16 * 8));
        }
    };

    // prefetch half of the U tile (64 rows x 128 cols fp32 = 32KB) into a freed stage
    auto load_u_half = [&](int half) {
        const float* Ub = U + (size_t)(bm * BM + half * 64) * GV + bn * BN;
        char* dstbase = smem + half * STG_BYTES;   // stage 'half' (0 or 1)
        #pragma unroll
        for (int i = 0; i < 16; i++) {
            int idx = tid + 128 * i;       // 0..2047 chunks
            int rr = idx >> 5, cc = idx & 31;   // rr 0..63 (local), cc chunk 0..31
            uint32_t d = (uint32_t)__cvta_generic_to_shared(
                dstbase + rr * 512 + ((cc ^ (rr & 7)) << 4));
            asm volatile("cp.async.cg.shared.global [%0], [%1], 16;\n"
                :: "r"(d), "l"(Ub + (size_t)rr * GV + cc * 4));
        }
    };

    // prefetch the emb tile (128 v x 8 d fp32 = 4KB) to EMBF (untouched by mainloop)
    {
        const float* eb = emb + ((size_t)g * V_DIM + v0) * DG;
        #pragma unroll
        for (int i = 0; i < 2; i++) {
            int idx = tid * 2 + i;         // 0..255 16B chunks
            uint32_t d = (uint32_t)__cvta_generic_to_shared(smem + EMBF_OFF + idx * 16);
            asm volatile("cp.async.cg.shared.global [%0], [%1], 16;\n"
                :: "r"(d), "l"(eb + idx * 4));
        }
    }

    float acc[4][8][4];
    #pragma unroll
    for (int a = 0; a < 4; a++)
        #pragma unroll
        for (int b = 0; b < 8; b++)
            #pragma unroll
            for (int c = 0; c < 4; c++) acc[a][b][c] = 0.f;

    const int NKT = KK / BK;  // 12
    #pragma unroll
    for (int kt = 0; kt < STAGES - 1; kt++) {
        load_stage(kt, kt);
        asm volatile("cp.async.commit_group;\n");
    }

    #pragma unroll 1
    for (int kt = 0; kt < NKT; kt++) {
        asm volatile("cp.async.wait_group 1;\n");
        __syncthreads();
        int pf = kt + STAGES - 1;
        if (pf < NKT) {
            load_stage(pf % STAGES, pf);
        } else {
            load_u_half(pf - NKT);   // kt=10 -> U rows 0-63, kt=11 -> rows 64-127
        }
        asm volatile("cp.async.commit_group;\n");

        int s = kt % STAGES;
        const char* sa = smem + s * STG_BYTES;
        const char* sb = sa + A_BYTES;
        #pragma unroll
        for (int kk = 0; kk < 4; kk++) {
            uint32_t a[4][4], b[8][2];
            int c16 = kk * 2 + (lane >> 4);
            #pragma unroll
            for (int mt = 0; mt < 4; mt++) {
                int row = wm * 64 + mt * 16 + (lane & 15);
                int pc  = c16 ^ (row & 7);
                uint32_t addr = (uint32_t)__cvta_generic_to_shared(sa + row * 128 + pc * 16);
                asm volatile("ldmatrix.sync.aligned.m8n8.x4.shared.b16 {%0,%1,%2,%3}, [%4];\n"
                    : "=r"(a[mt][0]), "=r"(a[mt][1]), "=r"(a[mt][2]), "=r"(a[mt][3]) : "r"(addr));
            }
            #pragma unroll
            for (int nb = 0; nb < 4; nb++) {
                int row = wn * 64 + nb * 16 + (lane & 15);
                int pc  = c16 ^ (row & 7);
                uint32_t addr = (uint32_t)__cvta_generic_to_shared(sb + row * 128 + pc * 16);
                uint32_t r0, r1, r2, r3;
                asm volatile("ldmatrix.sync.aligned.m8n8.x4.shared.b16 {%0,%1,%2,%3}, [%4];\n"
                    : "=r"(r0), "=r"(r1), "=r"(r2), "=r"(r3) : "r"(addr));
                b[nb * 2][0]     = r0; b[nb * 2 + 1][0] = r1;
                b[nb * 2][1]     = r2; b[nb * 2 + 1][1] = r3;
            }
            #pragma unroll
            for (int mt = 0; mt < 4; mt++)
                #pragma unroll
                for (int nt = 0; nt < 8; nt++) {
                    asm volatile("mma.sync.aligned.m16n8k16.row.col.f32.f16.f16.f32 "
                        "{%0,%1,%2,%3}, {%4,%5,%6,%7}, {%8,%9}, {%0,%1,%2,%3};\n"
                        : "+f"(acc[mt][nt][0]), "+f"(acc[mt][nt][1]),
                          "+f"(acc[mt][nt][2]), "+f"(acc[mt][nt][3])
                        : "r"(a[mt][0]), "r"(a[mt][1]), "r"(a[mt][2]), "r"(a[mt][3]),
                          "r"(b[nt][0]), "r"(b[nt][1]));
                }
        }
    }

    // ---- epilogue v6 ----
    asm volatile("cp.async.wait_group 0;\n");
    __syncthreads();   // U in stages 0-1, embF resident, stage2 free

    float* red = (float*)(smem + RED_OFF);   // [128 rows][2 wn][4]: sh, sy, max, idx

    // bias for this thread's 16 columns
    float2 bb[8];
    #pragma unroll
    for (int nt = 0; nt < 8; nt++) {
        int n = bn * BN + wn * 64 + nt * 8 + (lane & 3) * 2;
        bb[nt] = *(const float2*)(bias + n);
    }

    // phase 1: e, ey (fp32), reductions; ey tf32-rounded and stored in place
    #pragma unroll
    for (int mt = 0; mt < 4; mt++) {
        #pragma unroll
        for (int ch = 0; ch < 2; ch++) {
            int row_l = wm * 64 + mt * 16 + (lane >> 2) + ch * 8;
            size_t gb = (size_t)(bm * BM + row_l) * GV + bn * BN;
            float shp = 0.f, syp = 0.f, mxv = -1e30f;
            int mxi = 0;
            #pragma unroll
            for (int nt = 0; nt < 8; nt++) {
                int col2 = wn * 32 + nt * 4 + (lane & 3);   // float2 index 0..63
                float* up = (float*)(smem + USWZ(row_l, col2));
                float2 uv = *(float2*)up;
                float h0 = acc[mt][nt][ch * 2 + 0] + bb[nt].x;
                float h1 = acc[mt][nt][ch * 2 + 1] + bb[nt].y;
                float e0 = __expf(h0), e1 = __expf(h1);
                shp += e0 + e1;
                *(__half2*)(&g_E[gb + col2 * 2]) = __floats2half2_rn(e0, e1);
                float ey0 = __fdividef(e0, neg_log_u(uv.x));
                float ey1 = __fdividef(e1, neg_log_u(uv.y));
                syp += ey0 + ey1;
                if (ey0 > mxv) { mxv = ey0; mxi = col2 * 2; }
                if (ey1 > mxv) { mxv = ey1; mxi = col2 * 2 + 1; }
                *(float2*)up = make_float2(to_tf32(ey0), to_tf32(ey1));
            }
            // quad reductions (lanes of a quad hold the same row)
            #pragma unroll
            for (int o = 1; o <= 2; o <<= 1) {
                shp += __shfl_xor_sync(0xffffffffu, shp, o);
                syp += __shfl_xor_sync(0xffffffffu, syp, o);
                float omv = __shfl_xor_sync(0xffffffffu, mxv, o);
                int   omi = __shfl_xor_sync(0xffffffffu, mxi, o);
                if (omv > mxv || (omv == mxv && omi < mxi)) { mxv = omv; mxi = omi; }
            }
            if ((lane & 3) == 0) {
                *(float4*)(red + row_l * 8 + wn * 4) =
                    make_float4(shp, syp, mxv, (float)mxi);
            }
        }
    }
    // round embF to tf32 in place (thread tid owns v = tid)
    {
        float* ef = (float*)(smem + EMBF_OFF) + tid * 8;
        #pragma unroll
        for (int i = 0; i < 8; i++) ef[i] = to_tf32(ef[i]);
    }
    __syncthreads();

    // phase 2: cv via tf32 mma (m16n8k8). warp handles m-tiles (warp*2, warp*2+1).
    {
        int mt0 = warp * 2;
        int gq = lane >> 2;   // 0..7
        int tq = lane & 3;    // 0..3
        const float* ef = (const float*)(smem + EMBF_OFF);
        float ac[2][4] = {{0, 0, 0, 0}, {0, 0, 0, 0}};
        #pragma unroll
        for (int ks = 0; ks < 16; ks++) {
            int k0 = ks * 8;
            uint32_t b0 = __float_as_uint(ef[(k0 + tq) * 8 + gq]);
            uint32_t b1 = __float_as_uint(ef[(k0 + tq + 4) * 8 + gq]);
            #pragma unroll
            for (int t = 0; t < 2; t++) {
                int r1 = (mt0 + t) * 16 + gq;
                int c  = k0 + tq;
                int c2 = c + 4;
                uint32_t a0 = __float_as_uint(*(const float*)(smem + USWZ(r1,     c  >> 1) + (c  & 1) * 4));
                uint32_t a1 = __float_as_uint(*(const float*)(smem + USWZ(r1 + 8, c  >> 1) + (c  & 1) * 4));
                uint32_t a2 = __float_as_uint(*(const float*)(smem + USWZ(r1,     c2 >> 1) + (c2 & 1) * 4));
                uint32_t a3 = __float_as_uint(*(const float*)(smem + USWZ(r1 + 8, c2 >> 1) + (c2 & 1) * 4));
                asm volatile("mma.sync.aligned.m16n8k8.row.col.f32.tf32.tf32.f32 "
                    "{%0,%1,%2,%3}, {%4,%5,%6,%7}, {%8,%9}, {%0,%1,%2,%3};\n"
                    : "+f"(ac[t][0]), "+f"(ac[t][1]), "+f"(ac[t][2]), "+f"(ac[t][3])
                    : "r"(a0), "r"(a1), "r"(a2), "r"(a3), "r"(b0), "r"(b1));
            }
        }
        // scatter cv accumulators to cvs [row][8]
        float* cvs = (float*)(smem + CVS_OFF);
        #pragma unroll
        for (int t = 0; t < 2; t++) {
            int row = (mt0 + t) * 16 + gq;
            *(float2*)(cvs + row * 8 + tq * 2)       = make_float2(ac[t][0], ac[t][1]);
            *(float2*)(cvs + (row + 8) * 8 + tq * 2) = make_float2(ac[t][2], ac[t][3]);
        }
    }
    __syncthreads();

    // phase 3: thread = row; combine wn halves, write g_part
    {
        int row_l = tid;
        int m = bm * BM + row_l;
        float4 r0 = *(float4*)(red + row_l * 8);
        float4 r1 = *(float4*)(red + row_l * 8 + 4);
        float sh = r0.x + r1.x;
        float sy = r0.y + r1.y;
        float mxv = r0.z; float mxi = r0.w;
        if (r1.z > mxv || (r1.z == mxv && r1.w < mxi)) { mxv = r1.z; mxi = r1.w; }
        const float* cvs = (const float*)(smem + CVS_OFF) + row_l * 8;
        float4 c0 = ((const float4*)cvs)[0], c1 = ((const float4*)cvs)[1];
        float* P = g_part + ((size_t)m * 128 + bn) * 16;
        ((float4*)P)[0] = make_float4(sy, mxv, (float)v0 + mxi, sh);
        ((float4*)P)[1] = c0;
        ((float4*)P)[2] = c1;
    }
}

// ---------------- combine: reduce 64 tile-partials per (bt,g) ----------------
__global__ void __launch_bounds__(32) combine_kernel(
    const int* __restrict__ mask, float* __restrict__ out)
{
    int r = blockIdx.x;            // 0..8191
    int bt = r >> 1, gg = r & 1;
    int lane = threadIdx.x;
    const float* Pa = g_part + (((size_t)bt * 128) + gg * 64 + lane) * 16;
    const float* Pb = Pa + 32 * 16;
    float4 a0 = ((const float4*)Pa)[0], a1 = ((const float4*)Pa)[1], a2 = ((const float4*)Pa)[2];
    float4 b0 = ((const float4*)Pb)[0], b1 = ((const float4*)Pb)[1], b2 = ((const float4*)Pb)[2];
    float sy = a0.x + b0.x;
    float sh = a0.w + b0.w;
    float my = a0.y, vx = a0.z;
    if (b0.y > my || (b0.y == my && b0.z < vx)) { my = b0.y; vx = b0.z; }
    float cv[8];
    cv[0] = a1.x + b1.x; cv[1] = a1.y + b1.y; cv[2] = a1.z + b1.z; cv[3] = a1.w + b1.w;
    cv[4] = a2.x + b2.x; cv[5] = a2.y + b2.y; cv[6] = a2.z + b2.z; cv[7] = a2.w + b2.w;
    #pragma unroll
    for (int o = 16; o; o >>= 1) {
        sy += __shfl_xor_sync(0xffffffffu, sy, o);
        sh += __shfl_xor_sync(0xffffffffu, sh, o);
        float omy = __shfl_xor_sync(0xffffffffu, my, o);
        float ovx = __shfl_xor_sync(0xffffffffu, vx, o);
        if (omy > my || (omy == my && ovx < vx)) { my = omy; vx = ovx; }
        #pragma unroll
        for (int d = 0; d < 8; d++) cv[d] += __shfl_xor_sync(0xffffffffu, cv[d], o);
    }
    if (lane == 0) {
        float is = 1.f / sy;
        #pragma unroll
        for (int d = 0; d < 8; d++) out[bt * 16 + gg * 8 + d] = cv[d] * is;
        out[65537 + r] = vx;                                   // targets_idx
        g_R[r] = mask[bt] ? (g_inv_msum / sh) : 0.f;
    }
}

// ---------------- marginal column reduction (fp16 e, half2) ----------------
__global__ void __launch_bounds__(256) marg_kernel() {
    int c2 = blockIdx.x * 256 + threadIdx.x;   // 0..8191 column pairs
    int c  = c2 * 2;
    int g  = c >> 13;
    int bt0 = blockIdx.y * 256;
    float ax = 0.f, ay = 0.f;
    const __half2* Ep = (const __half2*)(g_E + (size_t)bt0 * GV + c);
    const float*   Rp = g_R + bt0 * 2 + g;
    #pragma unroll 4
    for (int i = 0; i < 256; ++i) {
        float2 e2 = __half22float2(*Ep);
        float r = *Rp;
        ax = fmaf(r, e2.x, ax);
        ay = fmaf(r, e2.y, ay);
        Ep += GV / 2;
        Rp += 2;
    }
    atomicAdd(&g_marg[c], ax);
    atomicAdd(&g_marg[c + 1], ay);
}

// ---------------- perplexity ----------------
__global__ void __launch_bounds__(256) final_kernel(float* __restrict__ out) {
    int t = threadIdx.x;
    float s0 = 0.f, s1v = 0.f;
    for (int c = t; c < V_DIM; c += 256) {
        float m = g_marg[c];
        s0 += m * my_logf(m + 1e-7f);
    }
    for (int c = V_DIM + t; c < GV; c += 256) {
        float m = g_marg[c];
        s1v += m * my_logf(m + 1e-7f);
    }
    __shared__ float sa[256], sb[256];
    sa[t] = s0; sb[t] = s1v; __syncthreads();
    for (int o = 128; o; o >>= 1) {
        if (t < o) { sa[t] += sa[t + o]; sb[t] += sb[t + o]; }
        __syncthreads();
    }
    if (t == 0) out[65536] = my_expf(-sa[0]) + my_expf(-sb[0]);
}

// ---------------- launch ----------------
extern "C" void kernel_launch(void* const* d_in, const int* in_sizes, int n_in,
                              void* d_out, int out_size) {
    const float* x    = (const float*)d_in[0];   // [8,512,256]
    const float* u    = (const float*)d_in[1];   // [8192, 8192]
    const float* emb  = (const float*)d_in[2];   // [1, 16384, 8]
    const float* W    = (const float*)d_in[3];   // [16384, 256]
    const float* bias = (const float*)d_in[4];   // [16384]
    const int*   mask = (const int*)d_in[5];     // [8,512]
    float* out = (float*)d_out;

    cudaFuncSetAttribute(gemm_kernel, cudaFuncAttributeMaxDynamicSharedMemorySize, GEMM_SMEM);

    prep_split<<<(GV * F_DIM + BT_N * F_DIM + 255) / 256, 256>>>(W, x);
    prep_misc<<<1, 256>>>(mask);

    dim3 ggrid(GV / BN, BT_N / BM);   // (128, 32)
    gemm_kernel<<<ggrid, 128, GEMM_SMEM>>>(bias, u, emb);

    combine_kernel<<<BT_N * 2, 32>>>(mask, out);

    dim3 mgrid(GV / 512, 16);
    marg_kernel<<<mgrid, 256>>>();

    final_kernel<<<1, 256>>>(out);
}

// round 17
// speedup vs baseline: 1.0394x; 1.0394x over previous
#include <cuda_runtime.h>
#include <cuda_fp16.h>
#include <cstdint>
#include <cstddef>

// ---------------- problem constants ----------------
#define BT_N   4096      // B*T
#define F_DIM  256
#define GV     16384     // G*V
#define V_DIM  8192
#define DG     8
#define KK     768       // 3 * F_DIM  (fp16-split GEMM packed along K)

// ---------------- scratch (device globals; no runtime allocation) ----------------
__device__ __half g_E[(size_t)BT_N * GV];               // 134 MB: exp(h) fp16 for marginal
__device__ float  g_part[(size_t)BT_N * 128 * 16];      // 33.5 MB per-(row,tile) partials
__device__ __half g_Asplit[(size_t)BT_N * KK];          // [xh | xh | xl]
__device__ __half g_Bsplit[(size_t)GV   * KK];          // [Wh | Wl | Wh]
__device__ float  g_R[BT_N * 2];                        // mask*inv_msum/Z per (bt,g)
__device__ float  g_marg[GV];                           // marginal accumulator
__device__ float  g_inv_msum;

// ---------------- FFMA log (final kernel) + exp ----------------
__device__ __forceinline__ float my_logf(float a) {
    float m, r, s, t, i, f;
    int e;
    e = (__float_as_int(a) - 0x3f2aaaab) & 0xff800000;
    m = __int_as_float(__float_as_int(a) - e);
    i = (float)e * 1.19209290e-7f;
    f = m - 1.0f;
    s = f * f;
    r = -0.130310059f;
    t =  0.140869141f;
    r = fmaf(r, s, -0.121483512f);
    t = fmaf(t, s,  0.139814854f);
    r = fmaf(r, s, -0.166846126f);
    t = fmaf(t, s,  0.200120345f);
    r = fmaf(r, s, -0.249996200f);
    r = fmaf(t, f, r);
    r = fmaf(r, f,  0.333331972f);
    r = fmaf(r, f, -0.500000000f);
    r = fmaf(r, s, f);
    r = fmaf(i, 0.693147182f, r);
    return r;
}

__device__ __forceinline__ float my_expf(float a) {
    float f, r, j;
    int i;
    j = fmaf(1.442695041f, a, 12582912.f) - 12582912.f;
    f = fmaf(j, -6.93145752e-1f, a);
    f = fmaf(j, -1.42860677e-6f, f);
    i = (int)j;
    r = 1.37805939e-3f;
    r = fmaf(r, f, 8.37312452e-3f);
    r = fmaf(r, f, 4.16695364e-2f);
    r = fmaf(r, f, 1.66664720e-1f);
    r = fmaf(r, f, 4.99999851e-1f);
    r = fmaf(r, f, 1.00000000e+0f);
    r = fmaf(r, f, 1.00000000e+0f);
    r = __int_as_float(__float_as_int(r) + (i << 23));
    return r;
}

// inner = -log(u); hybrid: MUFU for u<0.875, exact-f log1p Taylor for u>=0.875.
__device__ __forceinline__ float neg_log_u(float uu) {
    uu = fmaxf(uu, 1.17549435e-38f);
    float inner_m = -__logf(uu);
    float f = uu - 1.0f;                       // exact for uu >= 0.5 (Sterbenz)
    float q = fmaf(f, -0.125f, 0.14285714f);   // log1p Taylor deg 7
    q = fmaf(q, f, -0.16666667f);
    q = fmaf(q, f,  0.20f);
    q = fmaf(q, f, -0.25f);
    q = fmaf(q, f,  0.33333333f);
    q = fmaf(q, f, -0.5f);
    q = fmaf(q, f,  1.0f);
    float inner_p = -(f * q);
    return (uu >= 0.875f) ? inner_p : inner_m;
}

__device__ __forceinline__ float to_tf32(float x) {
    uint32_t v;
    asm("cvt.rna.tf32.f32 %0, %1;" : "=r"(v) : "f"(x));
    return __uint_as_float(v);
}

// ---------------- prep kernels ----------------
__global__ void prep_split(const float* __restrict__ W, const float* __restrict__ X) {
    int idx = blockIdx.x * blockDim.x + threadIdx.x;
    if (idx < GV * F_DIM) {
        int n = idx >> 8, k = idx & 255;
        float w = W[idx];
        __half hi = __float2half_rn(w);
        __half lo = __float2half_rn(w - __half2float(hi));
        size_t base = (size_t)n * KK;
        g_Bsplit[base + k]        = hi;
        g_Bsplit[base + 256 + k]  = lo;
        g_Bsplit[base + 512 + k]  = hi;
    } else if (idx < GV * F_DIM + BT_N * F_DIM) {
        int j = idx - GV * F_DIM;
        int n = j >> 8, k = j & 255;
        float x = X[j];
        __half hi = __float2half_rn(x);
        __half lo = __float2half_rn(x - __half2float(hi));
        size_t base = (size_t)n * KK;
        g_Asplit[base + k]        = hi;
        g_Asplit[base + 256 + k]  = hi;
        g_Asplit[base + 512 + k]  = lo;
    }
}

__global__ void prep_misc(const int* __restrict__ mask) {
    int t = threadIdx.x;
    for (int i = t; i < GV; i += 256) g_marg[i] = 0.f;
    int s = 0;
    for (int i = t; i < BT_N; i += 256) s += mask[i];
    __shared__ int sm[256];
    sm[t] = s; __syncthreads();
    for (int o = 128; o; o >>= 1) { if (t < o) sm[t] += sm[t + o]; __syncthreads(); }
    if (t == 0) g_inv_msum = 1.0f / (float)sm[0];
}

// ---------------- fused GEMM + epilogue ----------------
// Block tile 128x128, 4 warps, warp tile 64x64, BK=64, 3 stages, 2 CTAs/SM.
// Epilogue v8: U prefetched into freed stages; ey tf32 fp32 in place;
// e staged as fp16 in smem (stage2), flushed coalesced; cv by tf32 mma.
#define BM 128
#define BN 128
#define BK 64
#define STAGES 3
#define A_BYTES  (BM * BK * 2)          // 16384
#define STG_BYTES (2 * A_BYTES)         // 32768
#define E16_OFF  (2 * STG_BYTES)        // fp16 e tile 128x128x2 = 32768 (all of stage2)
#define EMBF_OFF (3 * STG_BYTES)        // emb fp32 tile 128x8 = 4KB
#define RED_OFF  (EMBF_OFF + 4096)      // 4KB
#define CVS_OFF  (RED_OFF + 4096)       // 4KB
#define GEMM_SMEM (CVS_OFF + 4096)      // 110592

// swizzled byte offset of float2 (row r, col-pair c2) within the 64KB U/ey region
#define USWZ(r, c2) ((r) * 512 + ((((c2) >> 1) ^ ((r) & 7)) << 4) + (((c2) & 1) << 3))
// swizzled byte offset within the fp16 e tile: row r, word w (w = half2 index 0..63)
#define E16SWZ(r, w) ((r) * 256 + (((w) ^ (((r) & 7) << 3)) << 2))

__global__ void __launch_bounds__(128, 2) gemm_kernel(
    const float* __restrict__ bias, const float* __restrict__ U,
    const float* __restrict__ emb)
{
    extern __shared__ __align__(128) char smem[];
    int tid  = threadIdx.x;
    int lane = tid & 31, warp = tid >> 5;
    int wm = warp >> 1, wn = warp & 1;        // 2 x 2 warp grid, warp tile 64x64
    int bm = blockIdx.y, bn = blockIdx.x;
    const __half* gA = g_Asplit + (size_t)bm * BM * KK;
    const __half* gB = g_Bsplit + (size_t)bn * BN * KK;

    const int g  = bn >> 6;
    const int v0 = (bn & 63) * 128;

    auto load_stage = [&](int s, int kt) {
        int k0 = kt * BK;
        char* sa = smem + s * STG_BYTES;
        char* sb = sa + A_BYTES;
        #pragma unroll
        for (int i = 0; i < 8; i++) {
            int idx = tid + 128 * i;       // 0..1023
            int row = idx >> 3, c16 = idx & 7;
            int pc  = c16 ^ (row & 7);
            uint32_t da = (uint32_t)__cvta_generic_to_shared(sa + row * 128 + pc * 16);
            asm volatile("cp.async.cg.shared.global [%0], [%1], 16;\n"
                :: "r"(da), "l"(gA + (size_t)row * KK + k0 + c16 * 8));
            uint32_t db = (uint32_t)__cvta_generic_to_shared(sb + row * 128 + pc * 16);
            asm volatile("cp.async.cg.shared.global [%0], [%1], 16;\n"
                :: "r"(db), "l"(gB + (size_t)row * KK + k0 + c16 * 8));
        }
    };

    // prefetch half of the U tile (64 rows x 128 cols fp32 = 32KB) into a freed stage
    auto load_u_half = [&](int half) {
        const float* Ub = U + (size_t)(bm * BM + half * 64) * GV + bn * BN;
        char* dstbase = smem + half * STG_BYTES;   // stage 'half' (0 or 1)
        #pragma unroll
        for (int i = 0; i < 16; i++) {
            int idx = tid + 128 * i;       // 0..2047 chunks
            int rr = idx >> 5, cc = idx & 31;   // rr 0..63 (local), cc chunk 0..31
            uint32_t d = (uint32_t)__cvta_generic_to_shared(
                dstbase + rr * 512 + ((cc ^ (rr & 7)) << 4));
            asm volatile("cp.async.cg.shared.global [%0], [%1], 16;\n"
                :: "r"(d), "l"(Ub + (size_t)rr * GV + cc * 4));
        }
    };

    // prefetch the emb tile (128 v x 8 d fp32 = 4KB) to EMBF (untouched by mainloop)
    {
        const float* eb = emb + ((size_t)g * V_DIM + v0) * DG;
        #pragma unroll
        for (int i = 0; i < 2; i++) {
            int idx = tid * 2 + i;         // 0..255 16B chunks
            uint32_t d = (uint32_t)__cvta_generic_to_shared(smem + EMBF_OFF + idx * 16);
            asm volatile("cp.async.cg.shared.global [%0], [%1], 16;\n"
                :: "r"(d), "l"(eb + idx * 4));
        }
    }

    float acc[4][8][4];
    #pragma unroll
    for (int a = 0; a < 4; a++)
        #pragma unroll
        for (int b = 0; b < 8; b++)
            #pragma unroll
            for (int c = 0; c < 4; c++) acc[a][b][c] = 0.f;

    const int NKT = KK / BK;  // 12
    #pragma unroll
    for (int kt = 0; kt < STAGES - 1; kt++) {
        load_stage(kt, kt);
        asm volatile("cp.async.commit_group;\n");
    }

    #pragma unroll 1
    for (int kt = 0; kt < NKT; kt++) {
        asm volatile("cp.async.wait_group 1;\n");
        __syncthreads();
        int pf = kt + STAGES - 1;
        if (pf < NKT) {
            load_stage(pf % STAGES, pf);
        } else {
            load_u_half(pf - NKT);   // kt=10 -> U rows 0-63, kt=11 -> rows 64-127
        }
        asm volatile("cp.async.commit_group;\n");

        int s = kt % STAGES;
        const char* sa = smem + s * STG_BYTES;
        const char* sb = sa + A_BYTES;
        #pragma unroll
        for (int kk = 0; kk < 4; kk++) {
            uint32_t a[4][4], b[8][2];
            int c16 = kk * 2 + (lane >> 4);
            #pragma unroll
            for (int mt = 0; mt < 4; mt++) {
                int row = wm * 64 + mt * 16 + (lane & 15);
                int pc  = c16 ^ (row & 7);
                uint32_t addr = (uint32_t)__cvta_generic_to_shared(sa + row * 128 + pc * 16);
                asm volatile("ldmatrix.sync.aligned.m8n8.x4.shared.b16 {%0,%1,%2,%3}, [%4];\n"
                    : "=r"(a[mt][0]), "=r"(a[mt][1]), "=r"(a[mt][2]), "=r"(a[mt][3]) : "r"(addr));
            }
            #pragma unroll
            for (int nb = 0; nb < 4; nb++) {
                int row = wn * 64 + nb * 16 + (lane & 15);
                int pc  = c16 ^ (row & 7);
                uint32_t addr = (uint32_t)__cvta_generic_to_shared(sb + row * 128 + pc * 16);
                uint32_t r0, r1, r2, r3;
                asm volatile("ldmatrix.sync.aligned.m8n8.x4.shared.b16 {%0,%1,%2,%3}, [%4];\n"
                    : "=r"(r0), "=r"(r1), "=r"(r2), "=r"(r3) : "r"(addr));
                b[nb * 2][0]     = r0; b[nb * 2 + 1][0] = r1;
                b[nb * 2][1]     = r2; b[nb * 2 + 1][1] = r3;
            }
            #pragma unroll
            for (int mt = 0; mt < 4; mt++)
                #pragma unroll
                for (int nt = 0; nt < 8; nt++) {
                    asm volatile("mma.sync.aligned.m16n8k16.row.col.f32.f16.f16.f32 "
                        "{%0,%1,%2,%3}, {%4,%5,%6,%7}, {%8,%9}, {%0,%1,%2,%3};\n"
                        : "+f"(acc[mt][nt][0]), "+f"(acc[mt][nt][1]),
                          "+f"(acc[mt][nt][2]), "+f"(acc[mt][nt][3])
                        : "r"(a[mt][0]), "r"(a[mt][1]), "r"(a[mt][2]), "r"(a[mt][3]),
                          "r"(b[nt][0]), "r"(b[nt][1]));
                }
        }
    }

    // ---- epilogue v8 ----
    asm volatile("cp.async.wait_group 0;\n");
    __syncthreads();   // U in stages 0-1, embF resident, stage2 free for e16

    float* red = (float*)(smem + RED_OFF);   // [128 rows][2 wn][4]: sh, sy, max, idx

    // bias for this thread's 16 columns
    float2 bb[8];
    #pragma unroll
    for (int nt = 0; nt < 8; nt++) {
        int n = bn * BN + wn * 64 + nt * 8 + (lane & 3) * 2;
        bb[nt] = *(const float2*)(bias + n);
    }

    // phase 1: e (fp16 -> smem), ey (tf32 fp32 in place), fp32 reductions
    #pragma unroll
    for (int mt = 0; mt < 4; mt++) {
        #pragma unroll
        for (int ch = 0; ch < 2; ch++) {
            int row_l = wm * 64 + mt * 16 + (lane >> 2) + ch * 8;
            float shp = 0.f, syp = 0.f, mxv = -1e30f;
            int mxi = 0;
            #pragma unroll
            for (int nt = 0; nt < 8; nt++) {
                int col2 = wn * 32 + nt * 4 + (lane & 3);   // float2 index 0..63
                float* up = (float*)(smem + USWZ(row_l, col2));
                float2 uv = *(float2*)up;
                float h0 = acc[mt][nt][ch * 2 + 0] + bb[nt].x;
                float h1 = acc[mt][nt][ch * 2 + 1] + bb[nt].y;
                float e0 = __expf(h0), e1 = __expf(h1);
                shp += e0 + e1;
                *(__half2*)(smem + E16_OFF + E16SWZ(row_l, col2)) = __floats2half2_rn(e0, e1);
                float ey0 = __fdividef(e0, neg_log_u(uv.x));
                float ey1 = __fdividef(e1, neg_log_u(uv.y));
                syp += ey0 + ey1;
                if (ey0 > mxv) { mxv = ey0; mxi = col2 * 2; }
                if (ey1 > mxv) { mxv = ey1; mxi = col2 * 2 + 1; }
                *(float2*)up = make_float2(to_tf32(ey0), to_tf32(ey1));
            }
            // quad reductions (lanes of a quad hold the same row)
            #pragma unroll
            for (int o = 1; o <= 2; o <<= 1) {
                shp += __shfl_xor_sync(0xffffffffu, shp, o);
                syp += __shfl_xor_sync(0xffffffffu, syp, o);
                float omv = __shfl_xor_sync(0xffffffffu, mxv, o);
                int   omi = __shfl_xor_sync(0xffffffffu, mxi, o);
                if (omv > mxv || (omv == mxv && omi < mxi)) { mxv = omv; mxi = omi; }
            }
            if ((lane & 3) == 0) {
                *(float4*)(red + row_l * 8 + wn * 4) =
                    make_float4(shp, syp, mxv, (float)mxi);
            }
        }
    }
    // round embF to tf32 in place (thread tid owns v = tid)
    {
        float* ef = (float*)(smem + EMBF_OFF) + tid * 8;
        #pragma unroll
        for (int i = 0; i < 8; i++) ef[i] = to_tf32(ef[i]);
    }
    __syncthreads();

    // flush fp16 e tile -> gmem, coalesced (uint4 = 8 cols; 16 lanes cover a row)
    {
        size_t gbase = (size_t)(bm * BM) * GV + bn * BN;
        #pragma unroll 4
        for (int p = 0; p < 16; p++) {
            int i = p * 128 + tid;          // 0..2047 uint4 chunks
            int row = i >> 4, q = i & 15;   // 16 uint4 per row
            uint4 val = *(uint4*)(smem + E16_OFF + row * 256 + (((q * 4) ^ ((row & 7) << 3)) << 2));
            *(uint4*)(&g_E[gbase + (size_t)row * GV + q * 8]) = val;
        }
    }

    // phase 2: cv via tf32 mma (m16n8k8). warp handles m-tiles (warp*2, warp*2+1).
    {
        int mt0 = warp * 2;
        int gq = lane >> 2;   // 0..7
        int tq = lane & 3;    // 0..3
        const float* ef = (const float*)(smem + EMBF_OFF);
        float ac[2][4] = {{0, 0, 0, 0}, {0, 0, 0, 0}};
        #pragma unroll
        for (int ks = 0; ks < 16; ks++) {
            int k0 = ks * 8;
            uint32_t b0 = __float_as_uint(ef[(k0 + tq) * 8 + gq]);
            uint32_t b1 = __float_as_uint(ef[(k0 + tq + 4) * 8 + gq]);
            #pragma unroll
            for (int t = 0; t < 2; t++) {
                int r1 = (mt0 + t) * 16 + gq;
                int c  = k0 + tq;
                int c2 = c + 4;
                uint32_t a0 = __float_as_uint(*(const float*)(smem + USWZ(r1,     c  >> 1) + (c  & 1) * 4));
                uint32_t a1 = __float_as_uint(*(const float*)(smem + USWZ(r1 + 8, c  >> 1) + (c  & 1) * 4));
                uint32_t a2 = __float_as_uint(*(const float*)(smem + USWZ(r1,     c2 >> 1) + (c2 & 1) * 4));
                uint32_t a3 = __float_as_uint(*(const float*)(smem + USWZ(r1 + 8, c2 >> 1) + (c2 & 1) * 4));
                asm volatile("mma.sync.aligned.m16n8k8.row.col.f32.tf32.tf32.f32 "
                    "{%0,%1,%2,%3}, {%4,%5,%6,%7}, {%8,%9}, {%0,%1,%2,%3};\n"
                    : "+f"(ac[t][0]), "+f"(ac[t][1]), "+f"(ac[t][2]), "+f"(ac[t][3])
                    : "r"(a0), "r"(a1), "r"(a2), "r"(a3), "r"(b0), "r"(b1));
            }
        }
        // scatter cv accumulators to cvs [row][8]
        float* cvs = (float*)(smem + CVS_OFF);
        #pragma unroll
        for (int t = 0; t < 2; t++) {
            int row = (mt0 + t) * 16 + gq;
            *(float2*)(cvs + row * 8 + tq * 2)       = make_float2(ac[t][0], ac[t][1]);
            *(float2*)(cvs + (row + 8) * 8 + tq * 2) = make_float2(ac[t][2], ac[t][3]);
        }
    }
    __syncthreads();

    // phase 3: thread = row; combine wn halves, write g_part
    {
        int row_l = tid;
        int m = bm * BM + row_l;
        float4 r0 = *(float4*)(red + row_l * 8);
        float4 r1 = *(float4*)(red + row_l * 8 + 4);
        float sh = r0.x + r1.x;
        float sy = r0.y + r1.y;
        float mxv = r0.z; float mxi = r0.w;
        if (r1.z > mxv || (r1.z == mxv && r1.w < mxi)) { mxv = r1.z; mxi = r1.w; }
        const float* cvs = (const float*)(smem + CVS_OFF) + row_l * 8;
        float4 c0 = ((const float4*)cvs)[0], c1 = ((const float4*)cvs)[1];
        float* P = g_part + ((size_t)m * 128 + bn) * 16;
        ((float4*)P)[0] = make_float4(sy, mxv, (float)v0 + mxi, sh);
        ((float4*)P)[1] = c0;
        ((float4*)P)[2] = c1;
    }
}

// ---------------- combine: reduce 64 tile-partials per (bt,g) ----------------
__global__ void __launch_bounds__(256) combine_kernel(
    const int* __restrict__ mask, float* __restrict__ out)
{
    int r = blockIdx.x * 8 + (threadIdx.x >> 5);   // 0..8191
    int bt = r >> 1, gg = r & 1;
    int lane = threadIdx.x & 31;
    const float* Pa = g_part + (((size_t)bt * 128) + gg * 64 + lane) * 16;
    const float* Pb = Pa + 32 * 16;
    float4 a0 = ((const float4*)Pa)[0], a1 = ((const float4*)Pa)[1], a2 = ((const float4*)Pa)[2];
    float4 b0 = ((const float4*)Pb)[0], b1 = ((const float4*)Pb)[1], b2 = ((const float4*)Pb)[2];
    float sy = a0.x + b0.x;
    float sh = a0.w + b0.w;
    float my = a0.y, vx = a0.z;
    if (b0.y > my || (b0.y == my && b0.z < vx)) { my = b0.y; vx = b0.z; }
    float cv[8];
    cv[0] = a1.x + b1.x; cv[1] = a1.y + b1.y; cv[2] = a1.z + b1.z; cv[3] = a1.w + b1.w;
    cv[4] = a2.x + b2.x; cv[5] = a2.y + b2.y; cv[6] = a2.z + b2.z; cv[7] = a2.w + b2.w;
    #pragma unroll
    for (int o = 16; o; o >>= 1) {
        sy += __shfl_xor_sync(0xffffffffu, sy, o);
        sh += __shfl_xor_sync(0xffffffffu, sh, o);
        float omy = __shfl_xor_sync(0xffffffffu, my, o);
        float ovx = __shfl_xor_sync(0xffffffffu, vx, o);
        if (omy > my || (omy == my && ovx < vx)) { my = omy; vx = ovx; }
        #pragma unroll
        for (int d = 0; d < 8; d++) cv[d] += __shfl_xor_sync(0xffffffffu, cv[d], o);
    }
    if (lane == 0) {
        float is = 1.f / sy;
        #pragma unroll
        for (int d = 0; d < 8; d++) out[bt * 16 + gg * 8 + d] = cv[d] * is;
        out[65537 + r] = vx;                                   // targets_idx
        g_R[r] = mask[bt] ? (g_inv_msum / sh) : 0.f;
    }
}

// ---------------- marginal column reduction (fp16 e, half2) ----------------
__global__ void __launch_bounds__(256) marg_kernel() {
    int c2 = blockIdx.x * 256 + threadIdx.x;   // 0..8191 column pairs
    int c  = c2 * 2;
    int g  = c >> 13;
    int bt0 = blockIdx.y * 128;
    float ax = 0.f, ay = 0.f;
    const __half2* Ep = (const __half2*)(g_E + (size_t)bt0 * GV + c);
    const float*   Rp = g_R + bt0 * 2 + g;
    #pragma unroll 4
    for (int i = 0; i < 128; ++i) {
        float2 e2 = __half22float2(*Ep);
        float r = *Rp;
        ax = fmaf(r, e2.x, ax);
        ay = fmaf(r, e2.y, ay);
        Ep += GV / 2;
        Rp += 2;
    }
    atomicAdd(&g_marg[c], ax);
    atomicAdd(&g_marg[c + 1], ay);
}

// ---------------- perplexity ----------------
__global__ void __launch_bounds__(256) final_kernel(float* __restrict__ out) {
    int t = threadIdx.x;
    float s0 = 0.f, s1v = 0.f;
    for (int c = t; c < V_DIM; c += 256) {
        float m = g_marg[c];
        s0 += m * my_logf(m + 1e-7f);
    }
    for (int c = V_DIM + t; c < GV; c += 256) {
        float m = g_marg[c];
        s1v += m * my_logf(m + 1e-7f);
    }
    __shared__ float sa[256], sb[256];
    sa[t] = s0; sb[t] = s1v; __syncthreads();
    for (int o = 128; o; o >>= 1) {
        if (t < o) { sa[t] += sa[t + o]; sb[t] += sb[t + o]; }
        __syncthreads();
    }
    if (t == 0) out[65536] = my_expf(-sa[0]) + my_expf(-sb[0]);
}

// ---------------- launch ----------------
extern "C" void kernel_launch(void* const* d_in, const int* in_sizes, int n_in,
                              void* d_out, int out_size) {
    const float* x    = (const float*)d_in[0];   // [8,512,256]
    const float* u    = (const float*)d_in[1];   // [8192, 8192]
    const float* emb  = (const float*)d_in[2];   // [1, 16384, 8]
    const float* W    = (const float*)d_in[3];   // [16384, 256]
    const float* bias = (const float*)d_in[4];   // [16384]
    const int*   mask = (const int*)d_in[5];     // [8,512]
    float* out = (float*)d_out;

    cudaFuncSetAttribute(gemm_kernel, cudaFuncAttributeMaxDynamicSharedMemorySize, GEMM_SMEM);

    prep_split<<<(GV * F_DIM + BT_N * F_DIM + 255) / 256, 256>>>(W, x);
    prep_misc<<<1, 256>>>(mask);

    dim3 ggrid(GV / BN, BT_N / BM);   // (128, 32)
    gemm_kernel<<<ggrid, 128, GEMM_SMEM>>>(bias, u, emb);

    combine_kernel<<<BT_N * 2 / 8, 256>>>(mask, out);

    dim3 mgrid(GV / 2 / 256, 32);     // (32, 32)
    marg_kernel<<<mgrid, 256>>>();

    final_kernel<<<1, 256>>>(out);
}